// round 11
// baseline (speedup 1.0000x reference)
#include <cuda_runtime.h>
#include <cstdint>
#include <math.h>

// ---------------------------------------------------------------------------
// cross_entropy_with_hnm_for_one_class_detection (GB300) — 6-kernel version
//
//   p1 = softmax(score)[:,1]; pos = l0>0.5; neg = l1>0.5
//   neg_prob = has_pos ? (neg ? p1 : 0) : p1
//   k = has_pos ? min(5*pos_num, neg_num) : N/10 ; thr = k-th smallest neg_prob
//   loss_score = [ sum_pos -l0*log p0 + sum_{neg_prob<=thr} -l1*log p1 ] / cnt
//   loss_bbox  = sum(((bbox - l[2:6])*mask[2:6])^2)/max(sum mask,1e-8) (0 if ==0)
//
// Exact k-th smallest via 12/10/10-bit radix select on float bits (candidates
// are non-negative floats => uint order == float order). Radix scans are
// recomputed per-block in kernel prologues (cheap, deterministic), removing
// all tiny scan/prep launches. Explicit k_init zeroes state each call.
// ---------------------------------------------------------------------------

#define BATCH 32
static const int MAXN0 = 32 * 320 * 320;   // 3,276,800
static const int MAXN1 = 32 * 160 * 160;   //   819,200
static const int MAXNT = MAXN0 + MAXN1;    // 4,096,000

struct BState {
    unsigned long long pos_num;
    unsigned long long neg_num;
    unsigned long long sel_cnt;   // selected count accumulated by k_final
    double pos_ce;                // sum_pos -l0*log p0
    double nonneg_w;              // sum_{!neg} -l1*log p1  (used when hp)
    double sel_ce;                // sum over k_final-selected elems of -l1*log p1
    double sq;
    double msum;
};

__device__ BState   g_state[2];
__device__ unsigned g_pu[MAXNT];           // bits(p1) | (neg << 31)
__device__ unsigned g_histA[2][4096];      // top-12-bit hist of p1, neg pixels
__device__ unsigned g_histB[2][4096];      // top-12-bit hist of p1, non-neg pixels
__device__ unsigned g_hist2[2][1024];      // level-2 bins
__device__ unsigned g_hist3[2][1024];      // level-3 bins

// ---------------------------------------------------------------------------
__global__ void k_init()
{
    int t = blockIdx.x * blockDim.x + threadIdx.x;
    int stride = gridDim.x * blockDim.x;
    for (int i = t; i < 2 * 4096; i += stride) (&g_histA[0][0])[i] = 0;
    for (int i = t; i < 2 * 4096; i += stride) (&g_histB[0][0])[i] = 0;
    for (int i = t; i < 2 * 1024; i += stride) (&g_hist2[0][0])[i] = 0;
    for (int i = t; i < 2 * 1024; i += stride) (&g_hist3[0][0])[i] = 0;
    unsigned* s = (unsigned*)g_state;
    int nw = (int)(sizeof(g_state) / 4);
    for (int i = t; i < nw; i += stride) s[i] = 0;
}

// ---------------------------------------------------------------------------
// Pass 1: all threshold-independent reductions + p1/neg scratch + both level-1
// histograms, hidden under the DRAM-bound mainloop (262 MB reads).
// Blocks [0,G0) -> branch 0, [G0,grid) -> branch 1; 4 pixels/thread/iter.
// ---------------------------------------------------------------------------
__global__ void k_pass1(const float* __restrict__ sc0, const float* __restrict__ bb0,
                        const float* __restrict__ gm0, const float* __restrict__ gl0,
                        const float* __restrict__ sc1, const float* __restrict__ bb1,
                        const float* __restrict__ gm1, const float* __restrict__ gl1,
                        int HW0, int HW1, int N0, int N1, int G0)
{
    __shared__ unsigned shA[4096];
    __shared__ unsigned shB[4096];
    for (int i = threadIdx.x; i < 4096; i += blockDim.x) { shA[i] = 0; shB[i] = 0; }
    __syncthreads();

    int br, lb, Gb, HW, Nb, gofs;
    const float *sc, *bb, *gm, *gl;
    if (blockIdx.x < G0) { br = 0; lb = blockIdx.x;      Gb = G0;             HW = HW0; Nb = N0; gofs = 0;  sc = sc0; bb = bb0; gm = gm0; gl = gl0; }
    else                 { br = 1; lb = blockIdx.x - G0; Gb = gridDim.x - G0; HW = HW1; Nb = N1; gofs = N0; sc = sc1; bb = bb1; gm = gm1; gl = gl1; }

    unsigned cpos = 0, cneg = 0;
    float a_posce = 0.f, a_nnw = 0.f, a_sq = 0.f, a_m = 0.f;

    int nq = Nb >> 2;
    int stride = Gb * blockDim.x;
    for (int q = lb * blockDim.x + threadIdx.x; q < nq; q += stride) {
        int i = q << 2;
        int n = i / HW;
        int s = i - n * HW;
        size_t b2 = (size_t)n * 2 * HW + s;
        size_t b4 = (size_t)n * 4 * HW + s;
        size_t b6 = (size_t)n * 6 * HW + s;

        float4 V0 = *reinterpret_cast<const float4*>(sc + b2);
        float4 V1 = *reinterpret_cast<const float4*>(sc + b2 + HW);
        float4 L0 = *reinterpret_cast<const float4*>(gl + b6);
        float4 L1 = *reinterpret_cast<const float4*>(gl + b6 + HW);

        float v0a[4] = {V0.x, V0.y, V0.z, V0.w};
        float v1a[4] = {V1.x, V1.y, V1.z, V1.w};
        float l0a[4] = {L0.x, L0.y, L0.z, L0.w};
        float l1a[4] = {L1.x, L1.y, L1.z, L1.w};
        unsigned outw[4];

        #pragma unroll
        for (int j = 0; j < 4; j++) {
            float d = v1a[j] - v0a[j];
            float e = expf(d);
            float denom = 1.0f + e;
            float p1 = __fdividef(e, denom);
            bool pos = l0a[j] > 0.5f;
            bool neg = l1a[j] > 0.5f;
            cpos += pos ? 1u : 0u;
            cneg += neg ? 1u : 0u;
            if (pos) a_posce += l0a[j] * logf(denom);     // -l0*log p0
            unsigned ub = __float_as_uint(p1);
            if (neg) atomicAdd(&shA[ub >> 20], 1u);
            else {
                atomicAdd(&shB[ub >> 20], 1u);
                a_nnw -= l1a[j] * logf(p1);               // -l1*log p1 over non-neg
            }
            outw[j] = ub | (neg ? 0x80000000u : 0u);
        }
        *reinterpret_cast<uint4*>(&g_pu[gofs + i]) =
            make_uint4(outw[0], outw[1], outw[2], outw[3]);

        #pragma unroll
        for (int c = 0; c < 4; c++) {
            float4 MK = *reinterpret_cast<const float4*>(gm + b6 + (size_t)(2 + c) * HW);
            float4 TG = *reinterpret_cast<const float4*>(gl + b6 + (size_t)(2 + c) * HW);
            float4 PV = *reinterpret_cast<const float4*>(bb + b4 + (size_t)c * HW);
            float mk[4] = {MK.x, MK.y, MK.z, MK.w};
            float tg[4] = {TG.x, TG.y, TG.z, TG.w};
            float pv[4] = {PV.x, PV.y, PV.z, PV.w};
            #pragma unroll
            for (int j = 0; j < 4; j++) {
                float dd = (pv[j] - tg[j]) * mk[j];
                a_sq += dd * dd;
                a_m  += mk[j];
            }
        }
    }
    __syncthreads();

    for (int i = threadIdx.x; i < 4096; i += blockDim.x) {
        if (shA[i]) atomicAdd(&g_histA[br][i], shA[i]);
        if (shB[i]) atomicAdd(&g_histB[br][i], shB[i]);
    }

    unsigned long long rp = cpos, rn = cneg;
    double dce = (double)a_posce, dnw = (double)a_nnw;
    double dsq = (double)a_sq, dm = (double)a_m;
    for (int o = 16; o > 0; o >>= 1) {
        rp  += __shfl_down_sync(0xffffffffu, rp, o);
        rn  += __shfl_down_sync(0xffffffffu, rn, o);
        dce += __shfl_down_sync(0xffffffffu, dce, o);
        dnw += __shfl_down_sync(0xffffffffu, dnw, o);
        dsq += __shfl_down_sync(0xffffffffu, dsq, o);
        dm  += __shfl_down_sync(0xffffffffu, dm, o);
    }
    if ((threadIdx.x & 31) == 0) {
        atomicAdd(&g_state[br].pos_num, rp);
        atomicAdd(&g_state[br].neg_num, rn);
        atomicAdd(&g_state[br].pos_ce, dce);
        atomicAdd(&g_state[br].nonneg_w, dnw);
        atomicAdd(&g_state[br].sq, dsq);
        atomicAdd(&g_state[br].msum, dm);
    }
}

// ---------------------------------------------------------------------------
// Block-prologue selection helpers (blockDim MUST be 256). All blocks compute
// identical results from the (now final) global histograms — deterministic.
// All branches are uniform across the block (they depend only on global
// state), so the early returns / __syncthreads() pairings are safe.
// ---------------------------------------------------------------------------
struct Sel1 { int hp; int need; unsigned prefix1; unsigned rem1; };

__device__ __forceinline__ Sel1 sel_level1(int br, int Nb,
                                           unsigned sh[4096], unsigned part[256],
                                           unsigned sres[2])
{
    Sel1 r;
    BState& st = g_state[br];
    unsigned long long pos = st.pos_num, neg = st.neg_num;
    unsigned long long N = (unsigned long long)Nb;
    r.hp = (pos > 0) ? 1 : 0;
    unsigned long long k;
    if (r.hp) { unsigned long long kp = 5ull * pos; k = (kp < neg) ? kp : neg; }
    else      { k = N / 10ull; }
    long long idx = (long long)k - 1;             // jnp.take default mode = clip
    if (idx < 0) idx = 0;
    if (idx > (long long)N - 1) idx = (long long)N - 1;
    unsigned long long rr = (unsigned long long)idx + 1;   // 1-indexed rank
    unsigned long long zeros = r.hp ? (N - neg) : 0ull;
    if (rr <= zeros) { r.need = 0; r.prefix1 = 0; r.rem1 = 0; return r; }
    r.need = 1;
    unsigned rrem = (unsigned)(rr - zeros);

    for (int i = threadIdx.x; i < 4096; i += 256) {
        unsigned c = g_histA[br][i];
        if (!r.hp) c += g_histB[br][i];
        sh[i] = c;
    }
    __syncthreads();
    unsigned ps = 0;
    #pragma unroll
    for (int j = 0; j < 16; j++) ps += sh[threadIdx.x * 16 + j];
    part[threadIdx.x] = ps;
    __syncthreads();
    if (threadIdx.x == 0) {
        unsigned long long cum = 0;
        int seg = 0;
        while (seg < 255 && cum + part[seg] < rrem) { cum += part[seg]; seg++; }
        int bin = seg * 16;
        while (bin < seg * 16 + 15 && cum + sh[bin] < rrem) { cum += sh[bin]; bin++; }
        sres[0] = (unsigned)bin;
        sres[1] = rrem - (unsigned)cum;
    }
    __syncthreads();
    r.prefix1 = sres[0];
    r.rem1    = sres[1];
    return r;
}

__device__ __forceinline__ void scan1024(const unsigned* gbins, unsigned rrem,
                                         unsigned sh[], unsigned part[], unsigned sres[2],
                                         unsigned& bin_out, unsigned& rem_out)
{
    for (int i = threadIdx.x; i < 1024; i += 256) sh[i] = gbins[i];
    __syncthreads();
    unsigned ps = 0;
    #pragma unroll
    for (int j = 0; j < 4; j++) ps += sh[threadIdx.x * 4 + j];
    part[threadIdx.x] = ps;
    __syncthreads();
    if (threadIdx.x == 0) {
        unsigned long long cum = 0;
        int seg = 0;
        while (seg < 255 && cum + part[seg] < rrem) { cum += part[seg]; seg++; }
        int bin = seg * 4;
        while (bin < seg * 4 + 3 && cum + sh[bin] < rrem) { cum += sh[bin]; bin++; }
        sres[0] = (unsigned)bin;
        sres[1] = rrem - (unsigned)cum;
    }
    __syncthreads();
    bin_out = sres[0];
    rem_out = sres[1];
}

// ---------------------------------------------------------------------------
// Level-2 histogram (bits [10:20) within level-1 bucket).
// ---------------------------------------------------------------------------
__global__ void k_histL2(int N0, int N1, int G0)
{
    __shared__ unsigned sh[4096];
    __shared__ unsigned part[256];
    __shared__ unsigned sres[2];

    int br, lb, Gb, Nb, gofs;
    if (blockIdx.x < G0) { br = 0; lb = blockIdx.x;      Gb = G0;             Nb = N0; gofs = 0;  }
    else                 { br = 1; lb = blockIdx.x - G0; Gb = gridDim.x - G0; Nb = N1; gofs = N0; }

    Sel1 sel = sel_level1(br, Nb, sh, part, sres);
    if (!sel.need) return;
    __syncthreads();

    unsigned* h2 = sh;                      // reuse first 1024 words
    for (int i = threadIdx.x; i < 1024; i += 256) h2[i] = 0;
    __syncthreads();

    int hp = sel.hp;
    unsigned prefix = sel.prefix1;
    int nq = Nb >> 2;
    int stride = Gb * 256;
    for (int q = lb * 256 + threadIdx.x; q < nq; q += stride) {
        uint4 w = *reinterpret_cast<const uint4*>(&g_pu[gofs + (q << 2)]);
        unsigned a[4] = {w.x, w.y, w.z, w.w};
        #pragma unroll
        for (int j = 0; j < 4; j++) {
            bool cand = hp ? (a[j] >> 31) : true;
            unsigned eb = a[j] & 0x7fffffffu;
            if (cand && (eb >> 20) == prefix)
                atomicAdd(&h2[(eb >> 10) & 1023u], 1u);
        }
    }
    __syncthreads();
    for (int i = threadIdx.x; i < 1024; i += 256)
        if (h2[i]) atomicAdd(&g_hist2[br][i], h2[i]);
}

// ---------------------------------------------------------------------------
// Level-3 histogram (bits [0:10) within level-2 bucket).
// ---------------------------------------------------------------------------
__global__ void k_histL3(int N0, int N1, int G0)
{
    __shared__ unsigned sh[4096];
    __shared__ unsigned part[256];
    __shared__ unsigned sres[2];

    int br, lb, Gb, Nb, gofs;
    if (blockIdx.x < G0) { br = 0; lb = blockIdx.x;      Gb = G0;             Nb = N0; gofs = 0;  }
    else                 { br = 1; lb = blockIdx.x - G0; Gb = gridDim.x - G0; Nb = N1; gofs = N0; }

    Sel1 sel = sel_level1(br, Nb, sh, part, sres);
    if (!sel.need) return;
    __syncthreads();

    unsigned bin2, rem2;
    scan1024(g_hist2[br], sel.rem1, sh, part, sres, bin2, rem2);
    unsigned prefix2 = (sel.prefix1 << 10) | bin2;   // 22-bit prefix
    __syncthreads();

    unsigned* h3 = sh;
    for (int i = threadIdx.x; i < 1024; i += 256) h3[i] = 0;
    __syncthreads();

    int hp = sel.hp;
    int nq = Nb >> 2;
    int stride = Gb * 256;
    for (int q = lb * 256 + threadIdx.x; q < nq; q += stride) {
        uint4 w = *reinterpret_cast<const uint4*>(&g_pu[gofs + (q << 2)]);
        unsigned a[4] = {w.x, w.y, w.z, w.w};
        #pragma unroll
        for (int j = 0; j < 4; j++) {
            bool cand = hp ? (a[j] >> 31) : true;
            unsigned eb = a[j] & 0x7fffffffu;
            if (cand && (eb >> 10) == prefix2)
                atomicAdd(&h3[eb & 1023u], 1u);
        }
    }
    __syncthreads();
    for (int i = threadIdx.x; i < 1024; i += 256)
        if (h3[i]) atomicAdd(&g_hist3[br][i], h3[i]);
}

// ---------------------------------------------------------------------------
// Final pass: resolve exact threshold in prologue, then accumulate
// -l1*log(p1) + count over selected elements. When hp, only selected NEG
// pixels matter here (non-negs were pre-accumulated in pass1); selected negs
// are few, so l1 gathers are sparse.
// ---------------------------------------------------------------------------
__global__ void k_final(const float* __restrict__ gl0, const float* __restrict__ gl1,
                        int HW0, int HW1, int N0, int N1, int G0)
{
    __shared__ unsigned sh[4096];
    __shared__ unsigned part[256];
    __shared__ unsigned sres[2];

    int br, lb, Gb, Nb, gofs, HW;
    const float* gl;
    if (blockIdx.x < G0) { br = 0; lb = blockIdx.x;      Gb = G0;             Nb = N0; gofs = 0;  HW = HW0; gl = gl0; }
    else                 { br = 1; lb = blockIdx.x - G0; Gb = gridDim.x - G0; Nb = N1; gofs = N0; HW = HW1; gl = gl1; }

    Sel1 sel = sel_level1(br, Nb, sh, part, sres);
    unsigned thr = 0;
    if (sel.need) {
        __syncthreads();
        unsigned bin2, rem2;
        scan1024(g_hist2[br], sel.rem1, sh, part, sres, bin2, rem2);
        __syncthreads();
        unsigned bin3, rem3;
        scan1024(g_hist3[br], rem2, sh, part, sres, bin3, rem3);
        thr = (((sel.prefix1 << 10) | bin2) << 10) | bin3;
    }

    BState& st = g_state[br];
    int hp = sel.hp;

    unsigned cnt = 0;
    float acc = 0.f;
    int nq = Nb >> 2;
    int stride = Gb * 256;
    for (int q = lb * 256 + threadIdx.x; q < nq; q += stride) {
        int i = q << 2;
        uint4 w = *reinterpret_cast<const uint4*>(&g_pu[gofs + i]);
        unsigned a[4] = {w.x, w.y, w.z, w.w};
        #pragma unroll
        for (int j = 0; j < 4; j++) {
            bool cand = hp ? (a[j] >> 31) : true;
            unsigned eb = a[j] & 0x7fffffffu;
            if (cand && eb <= thr) {
                int ii = i + j;
                int n = ii / HW;
                int s = ii - n * HW;
                float l1 = gl[((size_t)n * 6 + 1) * HW + s];
                acc -= l1 * logf(__uint_as_float(eb));
                cnt++;
            }
        }
    }

    unsigned long long rc = cnt;
    double da = (double)acc;
    for (int o = 16; o > 0; o >>= 1) {
        rc += __shfl_down_sync(0xffffffffu, rc, o);
        da += __shfl_down_sync(0xffffffffu, da, o);
    }
    if ((threadIdx.x & 31) == 0) {
        if (rc) atomicAdd(&st.sel_cnt, rc);
        atomicAdd(&st.sel_ce, da);
    }
}

// ---------------------------------------------------------------------------
// Finalize outputs.
// ---------------------------------------------------------------------------
__global__ void k_fin(float* out, int out_size, int N0, int N1)
{
    double tot = 0.0;
    double vals[4];
    for (int br = 0; br < 2; br++) {
        BState& st = g_state[br];
        unsigned long long N = (unsigned long long)(br ? N1 : N0);
        int hp = (st.pos_num > 0) ? 1 : 0;
        unsigned long long cnt;
        double ce;
        if (hp) {
            cnt = st.pos_num + (N - st.neg_num) + st.sel_cnt;
            ce  = st.pos_ce + st.nonneg_w + st.sel_ce;
        } else {
            cnt = st.pos_num + st.sel_cnt;
            ce  = st.pos_ce + st.sel_ce;
        }
        if (cnt < 1) cnt = 1;
        double ls = ce / (double)cnt;
        double denom = (st.msum > 1e-8) ? st.msum : 1e-8;
        double lb = (st.msum > 0.0) ? (st.sq / denom) : 0.0;
        vals[2 * br]     = ls;
        vals[2 * br + 1] = lb;
        tot += ls + lb;
    }
    if (out_size >= 1) out[0] = (float)tot;
    for (int j = 0; j < 4 && j + 1 < out_size; j++) out[j + 1] = (float)vals[j];
    for (int j = 5; j < out_size; j++) out[j] = 0.0f;
}

// ---------------------------------------------------------------------------
extern "C" void kernel_launch(void* const* d_in, const int* in_sizes, int n_in,
                              void* d_out, int out_size)
{
    const float* sc0 = (const float*)d_in[0];
    const float* bb0 = (const float*)d_in[1];
    const float* gm0 = (const float*)d_in[2];
    const float* gl0 = (const float*)d_in[3];
    const float* sc1 = (const float*)d_in[4];
    const float* bb1 = (const float*)d_in[5];
    const float* gm1 = (const float*)d_in[6];
    const float* gl1 = (const float*)d_in[7];

    int HW0 = in_sizes[0] / (BATCH * 2);
    int HW1 = in_sizes[4] / (BATCH * 2);
    int N0 = BATCH * HW0;
    int N1 = BATCH * HW1;

    // grid split proportional to N0:N1 = 4:1
    const int G0 = 592, G1 = 148, G = G0 + G1;
    const int T = 256;

    k_init  <<<32, T>>>();
    k_pass1 <<<G, T>>>(sc0, bb0, gm0, gl0, sc1, bb1, gm1, gl1, HW0, HW1, N0, N1, G0);
    k_histL2<<<G, T>>>(N0, N1, G0);
    k_histL3<<<G, T>>>(N0, N1, G0);
    k_final <<<G, T>>>(gl0, gl1, HW0, HW1, N0, N1, G0);
    k_fin   <<<1, 1>>>((float*)d_out, out_size, N0, N1);
}